// round 1
// baseline (speedup 1.0000x reference)
#include <cuda_runtime.h>
#include <math.h>

// Problem constants (from reference): B=4, S=2048, D=1024, E=8, K=2, H=2048
#define T_TOK 8192
#define D_DIM 1024
#define H_DIM 2048
#define E_NUM 8
#define A_TOT (2 * T_TOK)   // total assignments (top-2 per token) = 16384

// ---------------- scratch (static device globals; no allocations) ----------
__device__ int   g_topi[A_TOT];
__device__ float g_topw[A_TOT];
__device__ int   g_cnt[E_NUM];
__device__ int   g_off[E_NUM];
__device__ int   g_cursor[E_NUM];
__device__ int   g_perm[A_TOT];     // assignment slot -> token index
__device__ float g_pw[A_TOT];       // assignment slot -> combine weight
__device__ int   g_slot[A_TOT];     // (token,k) -> assignment slot
__device__ float g_h[(size_t)A_TOT * H_DIM];   // hidden activations, 134 MB
__device__ float g_y[(size_t)A_TOT * D_DIM];   // per-assignment outputs, 67 MB

// ---------------- kernel 1: zero the per-expert counters --------------------
__global__ void zero_kernel() {
    int i = threadIdx.x;
    if (i < E_NUM) { g_cnt[i] = 0; }
}

// ---------------- kernel 2: gating (softmax + top-2 + counts) --------------
// one warp per token; gate_w cached in smem (32 KB)
__global__ __launch_bounds__(256) void gating_kernel(
    const float* __restrict__ x,
    const float* __restrict__ gw,
    const float* __restrict__ gb)
{
    __shared__ float s_gw[D_DIM * E_NUM];
    int tid = threadIdx.x;
    for (int i = tid; i < D_DIM * E_NUM; i += blockDim.x) s_gw[i] = gw[i];
    __syncthreads();

    int warp = tid >> 5, lane = tid & 31;
    int t = blockIdx.x * 8 + warp;
    if (t >= T_TOK) return;

    float acc[E_NUM];
#pragma unroll
    for (int e = 0; e < E_NUM; e++) acc[e] = 0.f;

    const float* xr = x + (size_t)t * D_DIM;
    for (int d = lane; d < D_DIM; d += 32) {
        float xv = xr[d];
        const float* g = s_gw + d * E_NUM;
#pragma unroll
        for (int e = 0; e < E_NUM; e++) acc[e] += xv * g[e];
    }
#pragma unroll
    for (int e = 0; e < E_NUM; e++) {
#pragma unroll
        for (int o = 16; o > 0; o >>= 1)
            acc[e] += __shfl_xor_sync(0xffffffffu, acc[e], o);
    }

    if (lane == 0) {
        float logits[E_NUM];
#pragma unroll
        for (int e = 0; e < E_NUM; e++) logits[e] = acc[e] + gb[e];
        float mx = logits[0];
#pragma unroll
        for (int e = 1; e < E_NUM; e++) mx = fmaxf(mx, logits[e]);
        float p[E_NUM], s = 0.f;
#pragma unroll
        for (int e = 0; e < E_NUM; e++) { p[e] = expf(logits[e] - mx); s += p[e]; }
        float inv_s = 1.f / s;
#pragma unroll
        for (int e = 0; e < E_NUM; e++) p[e] *= inv_s;

        // top-2 (first index wins ties, matching jax top_k)
        int i0 = 0;
#pragma unroll
        for (int e = 1; e < E_NUM; e++) if (p[e] > p[i0]) i0 = e;
        int i1 = (i0 == 0) ? 1 : 0;
#pragma unroll
        for (int e = 0; e < E_NUM; e++)
            if (e != i0 && p[e] > p[i1]) i1 = e;

        float w0 = p[i0], w1 = p[i1];
        float inv = 1.f / (w0 + w1 + 1e-9f);
        g_topi[2 * t]     = i0;  g_topw[2 * t]     = w0 * inv;
        g_topi[2 * t + 1] = i1;  g_topw[2 * t + 1] = w1 * inv;
        atomicAdd(&g_cnt[i0], 1);
        atomicAdd(&g_cnt[i1], 1);
    }
}

// ---------------- kernel 3: exclusive prefix over 8 experts ----------------
__global__ void offsets_kernel() {
    if (threadIdx.x == 0) {
        int o = 0;
        for (int e = 0; e < E_NUM; e++) {
            g_off[e] = o;
            g_cursor[e] = o;
            o += g_cnt[e];
        }
    }
}

// ---------------- kernel 4: scatter assignments into per-expert groups -----
__global__ void scatter_kernel() {
    int a = blockIdx.x * blockDim.x + threadIdx.x;
    if (a >= A_TOT) return;
    int e = g_topi[a];
    int pos = atomicAdd(&g_cursor[e], 1);
    g_perm[pos] = a >> 1;         // token index
    g_pw[pos] = g_topw[a];
    g_slot[a] = pos;
}

// ---------------- kernel 5: grouped SGEMM1 (gather) + bias + relu ----------
// h[pos, :] = relu(x[perm[pos]] @ w1[e] + b1[e])  for pos in [off_e, off_e+cnt_e)
// tile 128x128x8, 256 threads, 8x8 microtile
__global__ __launch_bounds__(256) void gemm1_kernel(
    const float* __restrict__ x,
    const float* __restrict__ w1,
    const float* __restrict__ b1)
{
    int e = blockIdx.z;
    int cnt = g_cnt[e];
    int off = g_off[e];
    int m0 = blockIdx.x * 128;
    if (m0 >= cnt) return;
    int n0 = blockIdx.y * 128;

    const float* B = w1 + (size_t)e * D_DIM * H_DIM;

    __shared__ float As[8][128];
    __shared__ float Bs[8][128];

    int tid = threadIdx.x;
    int arow = tid >> 1;          // 0..127
    int acol4 = (tid & 1) * 4;    // 0 or 4
    int mg = m0 + arow;
    int pidx = off + (mg < cnt ? mg : 0);
    const float* Arow = x + (size_t)g_perm[pidx] * D_DIM;

    int brow = tid >> 5;          // 0..7
    int bcol4 = (tid & 31) * 4;   // 0..124

    int tx = tid & 15, ty = tid >> 4;
    float acc[8][8];
#pragma unroll
    for (int m = 0; m < 8; m++)
#pragma unroll
        for (int n = 0; n < 8; n++) acc[m][n] = 0.f;

    for (int kt = 0; kt < D_DIM; kt += 8) {
        float4 av = *(const float4*)(Arow + kt + acol4);
        float4 bv = *(const float4*)(B + (size_t)(kt + brow) * H_DIM + n0 + bcol4);
        __syncthreads();
        As[acol4 + 0][arow] = av.x;
        As[acol4 + 1][arow] = av.y;
        As[acol4 + 2][arow] = av.z;
        As[acol4 + 3][arow] = av.w;
        *(float4*)(&Bs[brow][bcol4]) = bv;
        __syncthreads();
#pragma unroll
        for (int k = 0; k < 8; k++) {
            float a[8], b[8];
            *(float4*)(a)     = *(const float4*)(&As[k][ty * 8]);
            *(float4*)(a + 4) = *(const float4*)(&As[k][ty * 8 + 4]);
            *(float4*)(b)     = *(const float4*)(&Bs[k][tx * 8]);
            *(float4*)(b + 4) = *(const float4*)(&Bs[k][tx * 8 + 4]);
#pragma unroll
            for (int m = 0; m < 8; m++)
#pragma unroll
                for (int n = 0; n < 8; n++) acc[m][n] += a[m] * b[n];
        }
    }

    const float* bias = b1 + e * H_DIM;
#pragma unroll
    for (int m = 0; m < 8; m++) {
        int mg2 = m0 + ty * 8 + m;
        if (mg2 >= cnt) continue;
        float* out = g_h + (size_t)(off + mg2) * H_DIM + n0 + tx * 8;
#pragma unroll
        for (int n = 0; n < 8; n++)
            out[n] = fmaxf(acc[m][n] + bias[n0 + tx * 8 + n], 0.f);
    }
}

// ---------------- kernel 6: grouped SGEMM2 + bias + combine-weight scale ---
// y[pos, :] = pw[pos] * (h[pos] @ w2[e] + b2[e])
__global__ __launch_bounds__(256) void gemm2_kernel(
    const float* __restrict__ w2,
    const float* __restrict__ b2)
{
    int e = blockIdx.z;
    int cnt = g_cnt[e];
    int off = g_off[e];
    int m0 = blockIdx.x * 128;
    if (m0 >= cnt) return;
    int n0 = blockIdx.y * 128;

    const float* B = w2 + (size_t)e * H_DIM * D_DIM;

    __shared__ float As[8][128];
    __shared__ float Bs[8][128];

    int tid = threadIdx.x;
    int arow = tid >> 1;
    int acol4 = (tid & 1) * 4;
    int mg = m0 + arow;
    int rr = off + (mg < cnt ? mg : 0);
    const float* Arow = g_h + (size_t)rr * H_DIM;

    int brow = tid >> 5;
    int bcol4 = (tid & 31) * 4;

    int tx = tid & 15, ty = tid >> 4;
    float acc[8][8];
#pragma unroll
    for (int m = 0; m < 8; m++)
#pragma unroll
        for (int n = 0; n < 8; n++) acc[m][n] = 0.f;

    for (int kt = 0; kt < H_DIM; kt += 8) {
        float4 av = *(const float4*)(Arow + kt + acol4);
        float4 bv = *(const float4*)(B + (size_t)(kt + brow) * D_DIM + n0 + bcol4);
        __syncthreads();
        As[acol4 + 0][arow] = av.x;
        As[acol4 + 1][arow] = av.y;
        As[acol4 + 2][arow] = av.z;
        As[acol4 + 3][arow] = av.w;
        *(float4*)(&Bs[brow][bcol4]) = bv;
        __syncthreads();
#pragma unroll
        for (int k = 0; k < 8; k++) {
            float a[8], b[8];
            *(float4*)(a)     = *(const float4*)(&As[k][ty * 8]);
            *(float4*)(a + 4) = *(const float4*)(&As[k][ty * 8 + 4]);
            *(float4*)(b)     = *(const float4*)(&Bs[k][tx * 8]);
            *(float4*)(b + 4) = *(const float4*)(&Bs[k][tx * 8 + 4]);
#pragma unroll
            for (int m = 0; m < 8; m++)
#pragma unroll
                for (int n = 0; n < 8; n++) acc[m][n] += a[m] * b[n];
        }
    }

    const float* bias = b2 + e * D_DIM;
#pragma unroll
    for (int m = 0; m < 8; m++) {
        int mg2 = m0 + ty * 8 + m;
        if (mg2 >= cnt) continue;
        float w = g_pw[off + mg2];
        float* out = g_y + (size_t)(off + mg2) * D_DIM + n0 + tx * 8;
#pragma unroll
        for (int n = 0; n < 8; n++)
            out[n] = w * (acc[m][n] + bias[n0 + tx * 8 + n]);
    }
}

// ---------------- kernel 7: deterministic combine --------------------------
// out[t, :] = y[slot[2t], :] + y[slot[2t+1], :]
__global__ __launch_bounds__(256) void combine_kernel(float* __restrict__ out) {
    int t = blockIdx.x;
    int tid = threadIdx.x;              // 256 threads * float4 = 1024 = D
    int s0 = g_slot[2 * t];
    int s1 = g_slot[2 * t + 1];
    const float4* y0 = (const float4*)(g_y + (size_t)s0 * D_DIM);
    const float4* y1 = (const float4*)(g_y + (size_t)s1 * D_DIM);
    float4 a = y0[tid], b = y1[tid];
    float4 r;
    r.x = a.x + b.x; r.y = a.y + b.y; r.z = a.z + b.z; r.w = a.w + b.w;
    ((float4*)(out + (size_t)t * D_DIM))[tid] = r;
}

// ---------------- launcher ---------------------------------------------------
// inputs (metadata order): 0:x [B,S,D] f32, 1:gate_w [D,E], 2:gate_b [E],
//                          3:w1 [E,D,H], 4:b1 [E,H], 5:w2 [E,H,D], 6:b2 [E,D]
extern "C" void kernel_launch(void* const* d_in, const int* in_sizes, int n_in,
                              void* d_out, int out_size) {
    const float* x      = (const float*)d_in[0];
    const float* gate_w = (const float*)d_in[1];
    const float* gate_b = (const float*)d_in[2];
    const float* w1     = (const float*)d_in[3];
    const float* b1     = (const float*)d_in[4];
    const float* w2     = (const float*)d_in[5];
    const float* b2     = (const float*)d_in[6];
    float* out = (float*)d_out;

    zero_kernel<<<1, 32>>>();
    gating_kernel<<<T_TOK / 8, 256>>>(x, gate_w, gate_b);
    offsets_kernel<<<1, 32>>>();
    scatter_kernel<<<A_TOT / 256, 256>>>();

    dim3 g1(T_TOK / 128, H_DIM / 128, E_NUM);   // (64, 16, 8)
    gemm1_kernel<<<g1, 256>>>(x, w1, b1);

    dim3 g2(T_TOK / 128, D_DIM / 128, E_NUM);   // (64, 8, 8)
    gemm2_kernel<<<g2, 256>>>(w2, b2);

    combine_kernel<<<T_TOK, 256>>>(out);
}

// round 6
// speedup vs baseline: 3.2467x; 3.2467x over previous
#include <cuda_runtime.h>
#include <math.h>
#include <stdint.h>

// Problem constants: B=4, S=2048, D=1024, E=8, K=2, H=2048
#define T_TOK 8192
#define D_DIM 1024
#define H_DIM 2048
#define E_NUM 8
#define A_TOT (2 * T_TOK)             // 16384 assignments
#define A_PAD (A_TOT + E_NUM * 128)   // 17408 padded rows
#define MT_TILES (A_PAD / 128)        // 136 m-tiles

// ---------------- scratch (device globals; no allocations) ------------------
__device__ int   g_topi[A_TOT];
__device__ float g_topw[A_TOT];
__device__ int   g_cnt[E_NUM];
__device__ int   g_poff[E_NUM + 1];
__device__ int   g_cursor[E_NUM];
__device__ int   g_perm[A_PAD];
__device__ float g_pw[A_PAD];
__device__ int   g_slot[A_TOT];
__device__ float g_xg[(size_t)A_PAD * D_DIM];   // gathered tokens, 71 MB
__device__ float g_h [(size_t)A_PAD * H_DIM];   // hidden, 142 MB
__device__ float g_y [(size_t)A_PAD * D_DIM];   // per-slot out, 71 MB

// ---------------- PTX helpers (generic sm_80+ only) -------------------------
__device__ __forceinline__ uint32_t smem_u32(const void* p) {
    uint32_t a;
    asm("{ .reg .u64 t; cvta.to.shared.u64 t, %1; cvt.u32.u64 %0, t; }" : "=r"(a) : "l"(p));
    return a;
}
__device__ __forceinline__ void cp_async16(uint32_t dst, const void* src) {
    asm volatile("cp.async.cg.shared.global [%0], [%1], 16;" :: "r"(dst), "l"(src) : "memory");
}
__device__ __forceinline__ void cp_commit() {
    asm volatile("cp.async.commit_group;" ::: "memory");
}
__device__ __forceinline__ uint32_t f2tf(float f) {
    uint32_t r;
    asm("cvt.rna.tf32.f32 %0, %1;" : "=r"(r) : "f"(f));
    return r;
}
__device__ __forceinline__ void mma_tf32(float* c, const uint32_t* a, const uint32_t* b) {
    asm volatile(
        "mma.sync.aligned.m16n8k8.row.col.f32.tf32.tf32.f32 "
        "{%0,%1,%2,%3}, {%4,%5,%6,%7}, {%8,%9}, {%0,%1,%2,%3};"
        : "+f"(c[0]), "+f"(c[1]), "+f"(c[2]), "+f"(c[3])
        : "r"(a[0]), "r"(a[1]), "r"(a[2]), "r"(a[3]), "r"(b[0]), "r"(b[1]));
}

// ---------------- kernel 1: zero counters ----------------------------------
__global__ void zero_kernel() {
    int i = threadIdx.x;
    if (i < E_NUM) g_cnt[i] = 0;
}

// ---------------- kernel 2: gating (softmax + top-2 + counts) --------------
__global__ __launch_bounds__(256) void gating_kernel(
    const float* __restrict__ x, const float* __restrict__ gw, const float* __restrict__ gb)
{
    __shared__ float s_gw[D_DIM * E_NUM];
    int tid = threadIdx.x;
    for (int i = tid; i < D_DIM * E_NUM; i += blockDim.x) s_gw[i] = gw[i];
    __syncthreads();

    int warp = tid >> 5, lane = tid & 31;
    int t = blockIdx.x * 8 + warp;
    if (t >= T_TOK) return;

    float acc[E_NUM];
#pragma unroll
    for (int e = 0; e < E_NUM; e++) acc[e] = 0.f;
    const float* xr = x + (size_t)t * D_DIM;
    for (int d = lane; d < D_DIM; d += 32) {
        float xv = xr[d];
        const float* g = s_gw + d * E_NUM;
#pragma unroll
        for (int e = 0; e < E_NUM; e++) acc[e] += xv * g[e];
    }
#pragma unroll
    for (int e = 0; e < E_NUM; e++)
#pragma unroll
        for (int o = 16; o > 0; o >>= 1)
            acc[e] += __shfl_xor_sync(0xffffffffu, acc[e], o);

    if (lane == 0) {
        float logits[E_NUM];
#pragma unroll
        for (int e = 0; e < E_NUM; e++) logits[e] = acc[e] + gb[e];
        float mx = logits[0];
#pragma unroll
        for (int e = 1; e < E_NUM; e++) mx = fmaxf(mx, logits[e]);
        float p[E_NUM], s = 0.f;
#pragma unroll
        for (int e = 0; e < E_NUM; e++) { p[e] = expf(logits[e] - mx); s += p[e]; }
        float inv_s = 1.f / s;
#pragma unroll
        for (int e = 0; e < E_NUM; e++) p[e] *= inv_s;

        int i0 = 0;
#pragma unroll
        for (int e = 1; e < E_NUM; e++) if (p[e] > p[i0]) i0 = e;
        int i1 = (i0 == 0) ? 1 : 0;
#pragma unroll
        for (int e = 0; e < E_NUM; e++)
            if (e != i0 && p[e] > p[i1]) i1 = e;

        float w0 = p[i0], w1 = p[i1];
        float inv = 1.f / (w0 + w1 + 1e-9f);
        g_topi[2 * t] = i0;     g_topw[2 * t] = w0 * inv;
        g_topi[2 * t + 1] = i1; g_topw[2 * t + 1] = w1 * inv;
        atomicAdd(&g_cnt[i0], 1);
        atomicAdd(&g_cnt[i1], 1);
    }
}

// ---------------- kernel 3: padded offsets ---------------------------------
__global__ void offsets_kernel() {
    if (threadIdx.x == 0) {
        int o = 0;
        for (int e = 0; e < E_NUM; e++) {
            g_poff[e] = o;
            g_cursor[e] = o;
            o += ((g_cnt[e] + 127) & ~127);
        }
        g_poff[E_NUM] = o;
    }
}

// ---------------- kernel 4: scatter ----------------------------------------
__global__ void scatter_kernel() {
    int a = blockIdx.x * blockDim.x + threadIdx.x;
    if (a >= A_TOT) return;
    int e = g_topi[a];
    int pos = atomicAdd(&g_cursor[e], 1);
    g_perm[pos] = a >> 1;
    g_pw[pos] = g_topw[a];
    g_slot[a] = pos;
}

// ---------------- kernel 5: gather tokens into padded groups ---------------
__global__ __launch_bounds__(256) void gather_kernel(const float* __restrict__ x) {
    int r = blockIdx.x;
    int tid = threadIdx.x;
    int e = 0;
#pragma unroll
    for (int i = 0; i < E_NUM; i++) if (r >= g_poff[i + 1]) e = i + 1;
    bool used = (e < E_NUM) && ((r - g_poff[e]) < g_cnt[e]);
    float4 v = make_float4(0.f, 0.f, 0.f, 0.f);
    if (used) v = ((const float4*)(x + (size_t)g_perm[r] * D_DIM))[tid];
    else if (tid == 0) g_pw[r] = 0.f;
    ((float4*)(g_xg + (size_t)r * D_DIM))[tid] = v;
}

// ---------------- mma.sync tf32 grouped GEMM --------------------------------
// Tile 128(M) x 128(N) x 16(Kstage). 256 threads = 8 warps (4m x 2n),
// warp tile 32x64, mma m16n8k8 tf32 (2 m-frag x 8 n-frag).
// A smem [m=128][k=16] stride 20 floats (conflict-free: bank=20*gid+tg).
// B smem [k=16][n=128] stride 136 floats (conflict-free: bank=8*tg+gid).
// MODE 0: g_h = relu(g_xg @ w1 + b1);  MODE 1: g_y = pw * (g_h @ w2 + b2)
#define A_STRIDE 20
#define B_STRIDE 136
#define A_STAGE_B (128 * A_STRIDE * 4)        // 10240
#define B_STAGE_B (16 * B_STRIDE * 4)         // 8704
#define STAGE_B (A_STAGE_B + B_STAGE_B)       // 18944
#define GEMM_SMEM (4 * STAGE_B)               // 75776

template<int KDIM, int NTOT, int MODE>
__global__ __launch_bounds__(256, 2) void moe_gemm_kernel(
    const float* __restrict__ W, const float* __restrict__ bias)
{
    constexpr int NK = KDIM / 16;
    extern __shared__ char smraw[];
    uint32_t smem_base = smem_u32(smraw);

    int tid = threadIdx.x, wid = tid >> 5, lane = tid & 31;
    int m0 = blockIdx.x * 128;

    int e = -1;
#pragma unroll
    for (int i = 0; i < E_NUM; i++)
        if (m0 >= g_poff[i] && m0 < g_poff[i + 1]) e = i;
    if (e < 0) return;
    int n0 = blockIdx.y * 128;

    const float* Abase = (MODE == 0 ? g_xg : g_h) + (size_t)m0 * KDIM;
    const float* Bbase = W + (size_t)e * KDIM * NTOT + n0;   // [k][n] row-major

    // stage loader: A 128x16 (4 chunks/row), B 16x128 (32 chunks/row)
    auto issue_stage = [&](int kt) {
        uint32_t sb = smem_base + (kt & 3) * STAGE_B;
        int k0 = kt * 16;
        {
            int i = tid, i2 = tid + 256;
            int r = i >> 2, c = i & 3;
            cp_async16(sb + (r * A_STRIDE + c * 4) * 4,
                       Abase + (size_t)r * KDIM + k0 + c * 4);
            r = i2 >> 2; c = i2 & 3;
            cp_async16(sb + (r * A_STRIDE + c * 4) * 4,
                       Abase + (size_t)r * KDIM + k0 + c * 4);
        }
        uint32_t sbB = sb + A_STAGE_B;
        {
            int i = tid, i2 = tid + 256;
            int k = i >> 5, c = i & 31;
            cp_async16(sbB + (k * B_STRIDE + c * 4) * 4,
                       Bbase + (size_t)(k0 + k) * NTOT + c * 4);
            k = i2 >> 5; c = i2 & 31;
            cp_async16(sbB + (k * B_STRIDE + c * 4) * 4,
                       Bbase + (size_t)(k0 + k) * NTOT + c * 4);
        }
        cp_commit();
    };

    issue_stage(0); issue_stage(1); issue_stage(2);

    int wm = wid & 3, wn = wid >> 2;          // 4 x 2 warp grid
    int gid = lane >> 2, tg = lane & 3;

    float acc[2][8][4];
#pragma unroll
    for (int mi = 0; mi < 2; mi++)
#pragma unroll
        for (int ni = 0; ni < 8; ni++)
#pragma unroll
            for (int q = 0; q < 4; q++) acc[mi][ni][q] = 0.f;

    for (int kt = 0; kt < NK; kt++) {
        asm volatile("cp.async.wait_group 2;" ::: "memory");
        __syncthreads();
        if (kt + 3 < NK) issue_stage(kt + 3);
        else cp_commit();

        const float* As = (const float*)(smraw + (kt & 3) * STAGE_B);
        const float* Bs = (const float*)(smraw + (kt & 3) * STAGE_B + A_STAGE_B);
#pragma unroll
        for (int k8 = 0; k8 < 16; k8 += 8) {
            uint32_t af[2][4], bf[8][2];
#pragma unroll
            for (int mi = 0; mi < 2; mi++) {
                int r = (wm * 32 + mi * 16 + gid) * A_STRIDE + k8 + tg;
                af[mi][0] = f2tf(As[r]);
                af[mi][1] = f2tf(As[r + 8 * A_STRIDE]);
                af[mi][2] = f2tf(As[r + 4]);
                af[mi][3] = f2tf(As[r + 8 * A_STRIDE + 4]);
            }
#pragma unroll
            for (int ni = 0; ni < 8; ni++) {
                int c = wn * 64 + ni * 8 + gid;
                bf[ni][0] = f2tf(Bs[(k8 + tg) * B_STRIDE + c]);
                bf[ni][1] = f2tf(Bs[(k8 + tg + 4) * B_STRIDE + c]);
            }
#pragma unroll
            for (int mi = 0; mi < 2; mi++)
#pragma unroll
                for (int ni = 0; ni < 8; ni++)
                    mma_tf32(acc[mi][ni], af[mi], bf[ni]);
        }
    }

    // epilogue: direct gmem stores (float2 per fragment row)
    float* Out = (MODE == 0 ? g_h : g_y);
    const float* be = bias + (size_t)e * NTOT + n0;
#pragma unroll
    for (int mi = 0; mi < 2; mi++) {
        int r0 = m0 + wm * 32 + mi * 16 + gid;
        int r1 = r0 + 8;
        float pw0 = 0.f, pw1 = 0.f;
        if (MODE == 1) { pw0 = g_pw[r0]; pw1 = g_pw[r1]; }
        float* o0 = Out + (size_t)r0 * NTOT + n0;
        float* o1 = Out + (size_t)r1 * NTOT + n0;
#pragma unroll
        for (int ni = 0; ni < 8; ni++) {
            int col = wn * 64 + ni * 8 + tg * 2;
            float2 bb = *(const float2*)(be + col);
            float v0 = acc[mi][ni][0] + bb.x;
            float v1 = acc[mi][ni][1] + bb.y;
            float v2 = acc[mi][ni][2] + bb.x;
            float v3 = acc[mi][ni][3] + bb.y;
            if (MODE == 0) {
                v0 = fmaxf(v0, 0.f); v1 = fmaxf(v1, 0.f);
                v2 = fmaxf(v2, 0.f); v3 = fmaxf(v3, 0.f);
            } else {
                v0 *= pw0; v1 *= pw0; v2 *= pw1; v3 *= pw1;
            }
            *(float2*)(o0 + col) = make_float2(v0, v1);
            *(float2*)(o1 + col) = make_float2(v2, v3);
        }
    }
}

// ---------------- kernel: deterministic combine ----------------------------
__global__ __launch_bounds__(256) void combine_kernel(float* __restrict__ out) {
    int t = blockIdx.x;
    int tid = threadIdx.x;
    int s0 = g_slot[2 * t];
    int s1 = g_slot[2 * t + 1];
    float4 a = ((const float4*)(g_y + (size_t)s0 * D_DIM))[tid];
    float4 b = ((const float4*)(g_y + (size_t)s1 * D_DIM))[tid];
    float4 r;
    r.x = a.x + b.x; r.y = a.y + b.y; r.z = a.z + b.z; r.w = a.w + b.w;
    ((float4*)(out + (size_t)t * D_DIM))[tid] = r;
}

// ---------------- launcher ---------------------------------------------------
extern "C" void kernel_launch(void* const* d_in, const int* in_sizes, int n_in,
                              void* d_out, int out_size) {
    const float* x      = (const float*)d_in[0];
    const float* gate_w = (const float*)d_in[1];
    const float* gate_b = (const float*)d_in[2];
    const float* w1     = (const float*)d_in[3];
    const float* b1     = (const float*)d_in[4];
    const float* w2     = (const float*)d_in[5];
    const float* b2     = (const float*)d_in[6];
    float* out = (float*)d_out;

    static bool attr_set = false;
    if (!attr_set) {
        cudaFuncSetAttribute(moe_gemm_kernel<D_DIM, H_DIM, 0>,
                             cudaFuncAttributeMaxDynamicSharedMemorySize, GEMM_SMEM);
        cudaFuncSetAttribute(moe_gemm_kernel<H_DIM, D_DIM, 1>,
                             cudaFuncAttributeMaxDynamicSharedMemorySize, GEMM_SMEM);
        attr_set = true;
    }

    zero_kernel<<<1, 32>>>();
    gating_kernel<<<T_TOK / 8, 256>>>(x, gate_w, gate_b);
    offsets_kernel<<<1, 32>>>();
    scatter_kernel<<<A_TOT / 256, 256>>>();
    gather_kernel<<<A_PAD, 256>>>(x);

    moe_gemm_kernel<D_DIM, H_DIM, 0><<<dim3(MT_TILES, H_DIM / 128), 256, GEMM_SMEM>>>(w1, b1);
    moe_gemm_kernel<H_DIM, D_DIM, 1><<<dim3(MT_TILES, D_DIM / 128), 256, GEMM_SMEM>>>(w2, b2);

    combine_kernel<<<T_TOK, 256>>>(out);
}

// round 9
// speedup vs baseline: 7.2523x; 2.2338x over previous
#include <cuda_runtime.h>
#include <cuda_fp16.h>
#include <math.h>
#include <stdint.h>

// Problem constants: B=4, S=2048, D=1024, E=8, K=2, H=2048
#define T_TOK 8192
#define D_DIM 1024
#define H_DIM 2048
#define E_NUM 8
#define A_TOT (2 * T_TOK)             // 16384 assignments
#define A_PAD (A_TOT + E_NUM * 128)   // 17408 padded rows
#define MT_TILES (A_PAD / 128)        // 136 m-tiles

// ---------------- scratch (device globals; no allocations) ------------------
__device__ int   g_topi[A_TOT];
__device__ float g_topw[A_TOT];
__device__ int   g_cnt[E_NUM];
__device__ int   g_poff[E_NUM + 1];
__device__ int   g_cursor[E_NUM];
__device__ int   g_perm[A_PAD];
__device__ float g_pw[A_PAD];
__device__ int   g_slot[A_TOT];
__device__ __half g_xh [(size_t)T_TOK * D_DIM];            // x fp16, 17 MB
__device__ __half g_w1h[(size_t)E_NUM * D_DIM * H_DIM];    // w1 fp16, 34 MB
__device__ __half g_w2h[(size_t)E_NUM * D_DIM * H_DIM];    // w2 fp16, 34 MB
__device__ __half g_h  [(size_t)A_PAD * H_DIM];            // hidden fp16, 71 MB
__device__ float  g_y  [(size_t)A_PAD * D_DIM];            // per-slot out, 71 MB

// ---------------- PTX helpers (generic sm_80+ only) -------------------------
__device__ __forceinline__ uint32_t smem_u32(const void* p) {
    uint32_t a;
    asm("{ .reg .u64 t; cvta.to.shared.u64 t, %1; cvt.u32.u64 %0, t; }" : "=r"(a) : "l"(p));
    return a;
}
__device__ __forceinline__ void cp_async16(uint32_t dst, const void* src) {
    asm volatile("cp.async.cg.shared.global [%0], [%1], 16;" :: "r"(dst), "l"(src) : "memory");
}
__device__ __forceinline__ void cp_commit() {
    asm volatile("cp.async.commit_group;" ::: "memory");
}
__device__ __forceinline__ void ldsm4(uint32_t* r, uint32_t a) {
    asm volatile("ldmatrix.sync.aligned.m8n8.x4.shared.b16 {%0,%1,%2,%3}, [%4];"
                 : "=r"(r[0]), "=r"(r[1]), "=r"(r[2]), "=r"(r[3]) : "r"(a));
}
__device__ __forceinline__ void ldsm4t(uint32_t* r, uint32_t a) {
    asm volatile("ldmatrix.sync.aligned.m8n8.x4.trans.shared.b16 {%0,%1,%2,%3}, [%4];"
                 : "=r"(r[0]), "=r"(r[1]), "=r"(r[2]), "=r"(r[3]) : "r"(a));
}
__device__ __forceinline__ void mma_f16(float* c, const uint32_t* a, const uint32_t* b) {
    asm volatile(
        "mma.sync.aligned.m16n8k16.row.col.f32.f16.f16.f32 "
        "{%0,%1,%2,%3}, {%4,%5,%6,%7}, {%8,%9}, {%0,%1,%2,%3};"
        : "+f"(c[0]), "+f"(c[1]), "+f"(c[2]), "+f"(c[3])
        : "r"(a[0]), "r"(a[1]), "r"(a[2]), "r"(a[3]), "r"(b[0]), "r"(b[1]));
}

// ---------------- kernel: zero counters ------------------------------------
__global__ void zero_kernel() {
    int i = threadIdx.x;
    if (i < E_NUM) g_cnt[i] = 0;
}

// ---------------- kernel: init padded perm/pw -------------------------------
__global__ __launch_bounds__(256) void initpad_kernel() {
    int i = blockIdx.x * 256 + threadIdx.x;
    if (i < A_PAD) { g_perm[i] = 0; g_pw[i] = 0.f; }
}

// ---------------- kernel: fp32 -> fp16 convert ------------------------------
__global__ __launch_bounds__(256) void cvt_kernel(const float* __restrict__ src,
                                                  __half2* __restrict__ dst) {
    int i = blockIdx.x * 256 + threadIdx.x;      // one float4 per thread
    float4 v = ((const float4*)src)[i];
    dst[2 * i]     = __floats2half2_rn(v.x, v.y);
    dst[2 * i + 1] = __floats2half2_rn(v.z, v.w);
}

// ---------------- kernel: gating (softmax + top-2 + counts) -----------------
__global__ __launch_bounds__(256) void gating_kernel(
    const float* __restrict__ x, const float* __restrict__ gw, const float* __restrict__ gb)
{
    __shared__ float s_gw[D_DIM * E_NUM];
    int tid = threadIdx.x;
    for (int i = tid; i < D_DIM * E_NUM; i += blockDim.x) s_gw[i] = gw[i];
    __syncthreads();

    int warp = tid >> 5, lane = tid & 31;
    int t = blockIdx.x * 8 + warp;
    if (t >= T_TOK) return;

    float acc[E_NUM];
#pragma unroll
    for (int e = 0; e < E_NUM; e++) acc[e] = 0.f;
    const float* xr = x + (size_t)t * D_DIM;
    for (int d = lane; d < D_DIM; d += 32) {
        float xv = xr[d];
        const float* g = s_gw + d * E_NUM;
#pragma unroll
        for (int e = 0; e < E_NUM; e++) acc[e] += xv * g[e];
    }
#pragma unroll
    for (int e = 0; e < E_NUM; e++)
#pragma unroll
        for (int o = 16; o > 0; o >>= 1)
            acc[e] += __shfl_xor_sync(0xffffffffu, acc[e], o);

    if (lane == 0) {
        float logits[E_NUM];
#pragma unroll
        for (int e = 0; e < E_NUM; e++) logits[e] = acc[e] + gb[e];
        float mx = logits[0];
#pragma unroll
        for (int e = 1; e < E_NUM; e++) mx = fmaxf(mx, logits[e]);
        float p[E_NUM], s = 0.f;
#pragma unroll
        for (int e = 0; e < E_NUM; e++) { p[e] = expf(logits[e] - mx); s += p[e]; }
        float inv_s = 1.f / s;
#pragma unroll
        for (int e = 0; e < E_NUM; e++) p[e] *= inv_s;

        int i0 = 0;
#pragma unroll
        for (int e = 1; e < E_NUM; e++) if (p[e] > p[i0]) i0 = e;
        int i1 = (i0 == 0) ? 1 : 0;
#pragma unroll
        for (int e = 0; e < E_NUM; e++)
            if (e != i0 && p[e] > p[i1]) i1 = e;

        float w0 = p[i0], w1 = p[i1];
        float inv = 1.f / (w0 + w1 + 1e-9f);
        g_topi[2 * t] = i0;     g_topw[2 * t] = w0 * inv;
        g_topi[2 * t + 1] = i1; g_topw[2 * t + 1] = w1 * inv;
        atomicAdd(&g_cnt[i0], 1);
        atomicAdd(&g_cnt[i1], 1);
    }
}

// ---------------- kernel: padded offsets -------------------------------------
__global__ void offsets_kernel() {
    if (threadIdx.x == 0) {
        int o = 0;
        for (int e = 0; e < E_NUM; e++) {
            g_poff[e] = o;
            g_cursor[e] = o;
            o += ((g_cnt[e] + 127) & ~127);
        }
        g_poff[E_NUM] = o;
    }
}

// ---------------- kernel: scatter --------------------------------------------
__global__ void scatter_kernel() {
    int a = blockIdx.x * blockDim.x + threadIdx.x;
    if (a >= A_TOT) return;
    int e = g_topi[a];
    int pos = atomicAdd(&g_cursor[e], 1);
    g_perm[pos] = a >> 1;
    g_pw[pos] = g_topw[a];
    g_slot[a] = pos;
}

// ---------------- fp16 mma grouped GEMM --------------------------------------
// Tile 128(M) x 128(N) x 32(Kstage). 256 threads = 8 warps (4m x 2n),
// warp tile 32x64, mma m16n8k16 fp16->fp32 (2 m-frag x 8 n-frag).
// A smem [128 m][32 k] half, row stride 80 B (5 chunks-slot, bank-complete r*5 mod 8).
// B smem [32 k][128 n] half, 256 B rows, 16B-chunk XOR swizzle c^(k&7).
// MODE 0: h = relu(xh[perm] @ w1h + b1)  (A gathered via g_perm)
// MODE 1: y = pw * (h @ w2h + b2)
#define A_STAGE_B (128 * 80)                  // 10240
#define B_STAGE_B (32 * 256)                  // 8192
#define STAGE_B (A_STAGE_B + B_STAGE_B)       // 18432
#define GEMM_SMEM (4 * STAGE_B)               // 73728

template<int KDIM, int NTOT, int MODE>
__global__ __launch_bounds__(256, 2) void moe_gemm_kernel(
    const __half* __restrict__ W, const float* __restrict__ bias)
{
    constexpr int NK = KDIM / 32;
    extern __shared__ char smraw[];
    __shared__ int s_perm[128];
    uint32_t smem_base = smem_u32(smraw);

    int tid = threadIdx.x, wid = tid >> 5, lane = tid & 31;
    int m0 = blockIdx.x * 128;

    int e = -1;
#pragma unroll
    for (int i = 0; i < E_NUM; i++)
        if (m0 >= g_poff[i] && m0 < g_poff[i + 1]) e = i;
    if (e < 0) return;
    int n0 = blockIdx.y * 128;

    if (MODE == 0) {
        if (tid < 128) s_perm[tid] = g_perm[m0 + tid];
        __syncthreads();
    }

    const __half* Ag = g_h + (size_t)m0 * KDIM;            // MODE 1 A base
    const __half* Bw = W + (size_t)e * KDIM * NTOT + n0;   // [k][n] row-major

    auto issue_stage = [&](int kt) {
        uint32_t sb = smem_base + (kt & 3) * STAGE_B;
        int k0 = kt * 32;
#pragma unroll
        for (int ii = 0; ii < 2; ii++) {                   // A: 512 chunks
            int i = tid + ii * 256;
            int m = i >> 2, c = i & 3;
            const __half* src = (MODE == 0)
                ? g_xh + (size_t)s_perm[m] * KDIM + k0 + c * 8
                : Ag + (size_t)m * KDIM + k0 + c * 8;
            cp_async16(sb + m * 80 + c * 16, src);
        }
        uint32_t sbB = sb + A_STAGE_B;
#pragma unroll
        for (int ii = 0; ii < 2; ii++) {                   // B: 512 chunks
            int i = tid + ii * 256;
            int k = i >> 4, c = i & 15;
            cp_async16(sbB + k * 256 + ((c ^ (k & 7)) << 4),
                       Bw + (size_t)(k0 + k) * NTOT + c * 8);
        }
        cp_commit();
    };

    issue_stage(0); issue_stage(1); issue_stage(2);

    int wm = wid & 3, wn = wid >> 2;
    int grp = lane >> 3, lrow = lane & 7;
    int rg = grp & 1, cg = grp >> 1;
    int gid = lane >> 2, tg = lane & 3;

    // per-lane address pieces
    uint32_t a_lane0 = (uint32_t)((wm * 32 + rg * 8 + lrow) * 80 + cg * 16);
    uint32_t b_row   = (uint32_t)((rg * 8 + lrow) * 256);

    float acc[2][8][4];
#pragma unroll
    for (int mi = 0; mi < 2; mi++)
#pragma unroll
        for (int ni = 0; ni < 8; ni++)
#pragma unroll
            for (int q = 0; q < 4; q++) acc[mi][ni][q] = 0.f;

    for (int kt = 0; kt < NK; kt++) {
        asm volatile("cp.async.wait_group 2;" ::: "memory");
        __syncthreads();
        if (kt + 3 < NK) issue_stage(kt + 3);
        else cp_commit();

        uint32_t sb = smem_base + (kt & 3) * STAGE_B;
        uint32_t sbB = sb + A_STAGE_B;
#pragma unroll
        for (int kc = 0; kc < 2; kc++) {                   // two k16 steps
            uint32_t a0[4], a1[4];
            ldsm4(a0, sb + a_lane0 + kc * 32);
            ldsm4(a1, sb + a_lane0 + 1280 + kc * 32);      // +16 rows * 80B
#pragma unroll
            for (int nt = 0; nt < 4; nt++) {
                uint32_t bfr[4];
                uint32_t c = (uint32_t)(wn * 8 + nt * 2 + cg);
                ldsm4t(bfr, sbB + b_row + kc * 4096 + ((c ^ (uint32_t)lrow) << 4));
                mma_f16(acc[0][nt * 2],     a0, bfr);
                mma_f16(acc[0][nt * 2 + 1], a0, bfr + 2);
                mma_f16(acc[1][nt * 2],     a1, bfr);
                mma_f16(acc[1][nt * 2 + 1], a1, bfr + 2);
            }
        }
    }

    const float* be = bias + (size_t)e * NTOT + n0;
    if (MODE == 0) {
        // store h as fp16
#pragma unroll
        for (int mi = 0; mi < 2; mi++) {
            int r0 = m0 + wm * 32 + mi * 16 + gid;
            int r1 = r0 + 8;
            __half* o0 = g_h + (size_t)r0 * NTOT + n0;
            __half* o1 = g_h + (size_t)r1 * NTOT + n0;
#pragma unroll
            for (int ni = 0; ni < 8; ni++) {
                int col = wn * 64 + (ni >> 1) * 16 + (ni & 1) * 8 + tg * 2;
                float2 bb = *(const float2*)(be + col);
                float v0 = fmaxf(acc[mi][ni][0] + bb.x, 0.f);
                float v1 = fmaxf(acc[mi][ni][1] + bb.y, 0.f);
                float v2 = fmaxf(acc[mi][ni][2] + bb.x, 0.f);
                float v3 = fmaxf(acc[mi][ni][3] + bb.y, 0.f);
                *(__half2*)(o0 + col) = __floats2half2_rn(v0, v1);
                *(__half2*)(o1 + col) = __floats2half2_rn(v2, v3);
            }
        }
    } else {
#pragma unroll
        for (int mi = 0; mi < 2; mi++) {
            int r0 = m0 + wm * 32 + mi * 16 + gid;
            int r1 = r0 + 8;
            float pw0 = g_pw[r0], pw1 = g_pw[r1];
            float* o0 = g_y + (size_t)r0 * NTOT + n0;
            float* o1 = g_y + (size_t)r1 * NTOT + n0;
#pragma unroll
            for (int ni = 0; ni < 8; ni++) {
                int col = wn * 64 + (ni >> 1) * 16 + (ni & 1) * 8 + tg * 2;
                float2 bb = *(const float2*)(be + col);
                *(float2*)(o0 + col) = make_float2(pw0 * (acc[mi][ni][0] + bb.x),
                                                   pw0 * (acc[mi][ni][1] + bb.y));
                *(float2*)(o1 + col) = make_float2(pw1 * (acc[mi][ni][2] + bb.x),
                                                   pw1 * (acc[mi][ni][3] + bb.y));
            }
        }
    }
}

// ---------------- kernel: deterministic combine ------------------------------
__global__ __launch_bounds__(256) void combine_kernel(float* __restrict__ out) {
    int t = blockIdx.x;
    int tid = threadIdx.x;
    int s0 = g_slot[2 * t];
    int s1 = g_slot[2 * t + 1];
    float4 a = ((const float4*)(g_y + (size_t)s0 * D_DIM))[tid];
    float4 b = ((const float4*)(g_y + (size_t)s1 * D_DIM))[tid];
    float4 r;
    r.x = a.x + b.x; r.y = a.y + b.y; r.z = a.z + b.z; r.w = a.w + b.w;
    ((float4*)(out + (size_t)t * D_DIM))[tid] = r;
}

// ---------------- launcher ----------------------------------------------------
extern "C" void kernel_launch(void* const* d_in, const int* in_sizes, int n_in,
                              void* d_out, int out_size) {
    const float* x      = (const float*)d_in[0];
    const float* gate_w = (const float*)d_in[1];
    const float* gate_b = (const float*)d_in[2];
    const float* w1     = (const float*)d_in[3];
    const float* b1     = (const float*)d_in[4];
    const float* w2     = (const float*)d_in[5];
    const float* b2     = (const float*)d_in[6];
    float* out = (float*)d_out;

    static bool attr_set = false;
    if (!attr_set) {
        cudaFuncSetAttribute(moe_gemm_kernel<D_DIM, H_DIM, 0>,
                             cudaFuncAttributeMaxDynamicSharedMemorySize, GEMM_SMEM);
        cudaFuncSetAttribute(moe_gemm_kernel<H_DIM, D_DIM, 1>,
                             cudaFuncAttributeMaxDynamicSharedMemorySize, GEMM_SMEM);
        attr_set = true;
    }

    // routing + conversions (independent streams of work, all on stream 0)
    zero_kernel<<<1, 32>>>();
    gating_kernel<<<T_TOK / 8, 256>>>(x, gate_w, gate_b);
    offsets_kernel<<<1, 32>>>();
    initpad_kernel<<<(A_PAD + 255) / 256, 256>>>();
    scatter_kernel<<<A_TOT / 256, 256>>>();

    __half* xh_p;  cudaGetSymbolAddress((void**)&xh_p,  g_xh);
    __half* w1h_p; cudaGetSymbolAddress((void**)&w1h_p, g_w1h);
    __half* w2h_p; cudaGetSymbolAddress((void**)&w2h_p, g_w2h);
    cvt_kernel<<<(T_TOK * D_DIM / 4) / 256, 256>>>(x, (__half2*)xh_p);
    cvt_kernel<<<(E_NUM * (size_t)D_DIM * H_DIM / 4) / 256, 256>>>(w1, (__half2*)w1h_p);
    cvt_kernel<<<(E_NUM * (size_t)D_DIM * H_DIM / 4) / 256, 256>>>(w2, (__half2*)w2h_p);

    moe_gemm_kernel<D_DIM, H_DIM, 0><<<dim3(MT_TILES, H_DIM / 128), 256, GEMM_SMEM>>>(w1h_p, b1);
    moe_gemm_kernel<H_DIM, D_DIM, 1><<<dim3(MT_TILES, D_DIM / 128), 256, GEMM_SMEM>>>(w2h_p, b2);

    combine_kernel<<<T_TOK, 256>>>(out);
}